// round 13
// baseline (speedup 1.0000x reference)
#include <cuda_runtime.h>
#include <cuda_bf16.h>
#include <math.h>

#define BB   128
#define SS   1024
#define TT   (BB*SS)          // 131072 tokens
#define IND  192
#define DD   64
#define EE   4
#define HID  256
#define NCLS 10

#define ATB 32768             // split activation tile: 128 rows x 256B
#define WTB 16384             // weight chunk: 64 rows x 256B (hi/lo pairs)

// ------------------------- scratch (device globals) ------------------------
__device__ float g_h1[(size_t)TT * DD];                // moe output buffer
__device__ __align__(16) unsigned g_hb[(size_t)TT * 32]; // h as bf16 pairs
__device__ float g_gate[TT];
__device__ int   g_idx[(size_t)EE * TT];
__device__ int   g_cnt[EE];
__device__ float g_psum[EE];
__device__ float g_z[BB * DD];
// pre-split bf16 weights, 36 chunks, swizzled smem image [n][kw] uint2{hi,lo}
__device__ __align__(16) char g_wsp[(size_t)36 * WTB];
// pre-split x: 1024 token-tiles x 3 K-chunks, exact swizzled smem images
__device__ __align__(16) char g_xs[(size_t)3072 * ATB];

__device__ __forceinline__ float gelu_f(float v) {
    return 0.5f * v * (1.0f + erff(v * 0.70710678118654752440f));
}
__device__ __forceinline__ uint2 split_bf2(float x0, float x1) {
    __nv_bfloat16 h0 = __float2bfloat16_rn(x0), h1 = __float2bfloat16_rn(x1);
    float f0 = __bfloat162float(h0), f1 = __bfloat162float(h1);
    __nv_bfloat16 l0 = __float2bfloat16_rn(x0 - f0), l1 = __float2bfloat16_rn(x1 - f1);
    uint2 r;
    r.x = ((unsigned)__bfloat16_as_ushort(h1) << 16) | __bfloat16_as_ushort(h0);
    r.y = ((unsigned)__bfloat16_as_ushort(l1) << 16) | __bfloat16_as_ushort(l0);
    return r;
}
__device__ __forceinline__ unsigned pack_bf2(float x0, float x1) {
    __nv_bfloat162 p = __floats2bfloat162_rn(x0, x1);
    return *(unsigned*)&p;
}
// split-tile addressing (256B rows): word w (0..31 = k-pair), pairs (w,w+4)
__device__ __forceinline__ int aphys(int w) {
    int u = w & 7;
    return ((w >> 3) << 6) + (((((u & 3) << 1) | (u >> 2))) << 3);
}
__device__ __forceinline__ int aoff(int row, int w) {
    return row * 256 + (aphys(w) ^ ((row & 1) << 6));
}
__device__ __forceinline__ unsigned su32(const void* p) {
    return (unsigned)__cvta_generic_to_shared(p);
}
__device__ __forceinline__ void cpa16(unsigned dst, const void* src) {
    asm volatile("cp.async.cg.shared.global [%0], [%1], 16;" :: "r"(dst), "l"(src));
}
#define CPA_COMMIT() asm volatile("cp.async.commit_group;" ::: "memory")
#define CPA_WAIT0()  asm volatile("cp.async.wait_group 0;" ::: "memory")
#define CPA_WAIT1()  asm volatile("cp.async.wait_group 1;" ::: "memory")

__device__ __forceinline__ void stage_ws_async(char* dst, const char* src, int t) {
    unsigned d = su32(dst);
    for (int i = t; i < WTB / 16; i += 256)
        cpa16(d + i * 16, src + i * 16);
}
__device__ __forceinline__ void stage_xs_async(char* dst, const char* src, int t) {
    unsigned d = su32(dst);
    for (int i = t; i < ATB / 16; i += 256)
        cpa16(d + i * 16, src + i * 16);
}

__device__ __forceinline__ void mmabf(float* c, const unsigned* a, unsigned b0, unsigned b1) {
    asm volatile(
        "mma.sync.aligned.m16n8k16.row.col.f32.bf16.bf16.f32 "
        "{%0,%1,%2,%3},{%4,%5,%6,%7},{%8,%9},{%0,%1,%2,%3};"
        : "+f"(c[0]), "+f"(c[1]), "+f"(c[2]), "+f"(c[3])
        : "r"(a[0]), "r"(a[1]), "r"(a[2]), "r"(a[3]), "r"(b0), "r"(b1));
}
__device__ __forceinline__ void mma3bf(float* c, const unsigned* aH, const unsigned* aL,
                                       unsigned bH0, unsigned bH1,
                                       unsigned bL0, unsigned bL1) {
    mmabf(c, aL, bH0, bH1);
    mmabf(c, aH, bL0, bL1);
    mmabf(c, aH, bH0, bH1);
}
__device__ __forceinline__ void ldm4(unsigned* a, unsigned addr) {
    asm volatile("ldmatrix.sync.aligned.m8n8.x4.shared.b16 {%0,%1,%2,%3}, [%4];"
        : "=r"(a[0]), "=r"(a[1]), "=r"(a[2]), "=r"(a[3]) : "r"(addr));
}

// ---- k12 GEMM: x3 over split tiles ----------------------------------------
__device__ __forceinline__ void gemm_m32n32(float acc[2][4][4],
                                            const char* A, const char* W,
                                            int row0, int nb, int g, int tg) {
    const int pg = (g & 1) << 6;
    const char* a0p = A + (row0 + g) * 256;
    const char* a1p = A + (row0 + 8 + g) * 256;
    const char* a2p = A + (row0 + 16 + g) * 256;
    const char* a3p = A + (row0 + 24 + g) * 256;
    const char* bp  = W + (nb + g) * 256;
#pragma unroll
    for (int kg = 0; kg < 4; ++kg) {
        int C = ((kg << 6) ^ pg) + (tg << 4);
        uint4 A0 = *(const uint4*)(a0p + C);
        uint4 A1 = *(const uint4*)(a1p + C);
        uint4 A2 = *(const uint4*)(a2p + C);
        uint4 A3 = *(const uint4*)(a3p + C);
        unsigned aH0[4] = {A0.x, A1.x, A0.z, A1.z};
        unsigned aL0[4] = {A0.y, A1.y, A0.w, A1.w};
        unsigned aH1[4] = {A2.x, A3.x, A2.z, A3.z};
        unsigned aL1[4] = {A2.y, A3.y, A2.w, A3.w};
#pragma unroll
        for (int j = 0; j < 4; ++j) {
            uint4 B = *(const uint4*)(bp + j * 2048 + C);
            mma3bf(acc[0][j], aH0, aL0, B.x, B.z, B.y, B.w);
            mma3bf(acc[1][j], aH1, aL1, B.x, B.z, B.y, B.w);
        }
    }
}

// ---- k3 GEMM: A plain bf16 (ldmatrix, 128B rows), B x2 hi/lo ---------------
__device__ __forceinline__ void gemm_x1(float acc[2][4][4],
                                        unsigned Abase, const char* W,
                                        int row0, int nb, int lane) {
    const int g = lane >> 2, tg = lane & 3;
    const int li = lane & 7, grp = lane >> 3;
    const int rsub = ((grp & 1) << 3) + li;
    const int khalf = (grp >> 1) << 4;
    const int r0a = row0 + rsub, r1a = row0 + 16 + rsub;
    const unsigned a0base = Abase + r0a * 128;
    const unsigned a1base = Abase + r1a * 128;
    const int sw0 = (r0a & 7) << 4, sw1 = (r1a & 7) << 4;
    const char* bp = W + (nb + g) * 256;
    const int pg = (g & 1) << 6;
#pragma unroll
    for (int kg = 0; kg < 4; ++kg) {
        int kb = kg * 32 + khalf;
        unsigned A0[4], A1[4];
        ldm4(A0, a0base + (unsigned)(kb ^ sw0));
        ldm4(A1, a1base + (unsigned)(kb ^ sw1));
        int C = ((kg << 6) ^ pg) + (tg << 4);
#pragma unroll
        for (int j = 0; j < 4; ++j) {
            uint4 B = *(const uint4*)(bp + j * 2048 + C);
            mmabf(acc[0][j], A0, B.x, B.z);
            mmabf(acc[0][j], A0, B.y, B.w);
            mmabf(acc[1][j], A1, B.x, B.z);
            mmabf(acc[1][j], A1, B.y, B.w);
        }
    }
}

// ------------------------- k_pre: split+layout all weights ------------------
__global__ void __launch_bounds__(256) k_pre(const float* __restrict__ pw1,
                                             const float* __restrict__ pw2,
                                             const float* __restrict__ ew1,
                                             const float* __restrict__ ew2) {
    const int cid = blockIdx.x, t = threadIdx.x;
    char* dst = g_wsp + (size_t)cid * WTB;
#pragma unroll
    for (int p = 0; p < 8; ++p) {
        int idx = p * 256 + t;
        int kw = idx >> 6, n = idx & 63;
        int k0 = 2 * kw, k1 = 2 * kw + 1;
        float v0, v1;
        if (cid < 3) {
            v0 = pw1[(size_t)(cid * 64 + k0) * DD + n];
            v1 = pw1[(size_t)(cid * 64 + k1) * DD + n];
        } else if (cid == 3) {
            v0 = pw2[(size_t)k0 * DD + n];
            v1 = pw2[(size_t)k1 * DD + n];
        } else if (cid < 20) {
            int e = (cid - 4) >> 2, ch = (cid - 4) & 3;
            const float* w = ew1 + (size_t)e * DD * HID + ch * 64 + n;
            v0 = w[(size_t)k0 * HID];
            v1 = w[(size_t)k1 * HID];
        } else {
            int e = (cid - 20) >> 2, ch = (cid - 20) & 3;
            const float* w = ew2 + (size_t)e * HID * DD + (size_t)ch * 64 * DD + n;
            v0 = w[(size_t)k0 * DD];
            v1 = w[(size_t)k1 * DD];
        }
        *(uint2*)(dst + aoff(n, kw)) = split_bf2(v0, v1);
    }
}

// ------------------- k_xsplit: x -> swizzled split tiles --------------------
// grid (1024, 3): token-tile tb, K-chunk it. Thread = (row, half).
// beat bb (0..15) at row*256 + (bb*16 ^ ((row&1)<<6)) holds k-pairs
// w = (bb>>2)*8 + (bb&3) and w+4.
__global__ void __launch_bounds__(256) k_xsplit(const float* __restrict__ x) {
    const int tb = blockIdx.x, it = blockIdx.y;
    const int t = threadIdx.x;
    const int row = t >> 1, half = t & 1;
    const float* src = x + (size_t)(tb * 128 + row) * IND + it * 64 + half * 32;
    char* dst = g_xs + ((size_t)tb * 3 + it) * ATB + row * 256;
    const int xr = (row & 1) << 6;
    float4 v[8];
#pragma unroll
    for (int q = 0; q < 8; ++q) v[q] = *(const float4*)(src + q * 4);
    const float* vf = (const float*)v;
#pragma unroll
    for (int b = 0; b < 8; ++b) {
        int bb = half * 8 + b;
        int wlo = (bb >> 2) * 8 + (bb & 3);   // global k-pair index
        int lw = wlo - half * 16;              // local pair (0..11)
        uint2 p0 = split_bf2(vf[2 * lw], vf[2 * lw + 1]);
        uint2 p1 = split_bf2(vf[2 * (lw + 4)], vf[2 * (lw + 4) + 1]);
        uint4 beat; beat.x = p0.x; beat.y = p0.y; beat.z = p1.x; beat.w = p1.y;
        *(uint4*)(dst + ((bb * 16) ^ xr)) = beat;
    }
}

// ------------------------- k0: zero counters -------------------------------
__global__ void k0_zero() {
    int t = threadIdx.x;
    if (t < EE) { g_cnt[t] = 0; g_psum[t] = 0.0f; }
}

// ------------- k12: fused patch-encoder (both layers) + gate ---------------
// dyn smem: xs0 @0 | ws0 @32768 | xs1 @49152 | ws1 @81920  (98304 B)
// gate scratch hsf (128x65 fp32) overlays xs0+ws0 (dead at gate time)
extern __shared__ char sm12[];
__global__ void __launch_bounds__(256, 2) k12_pe_gate(const float* __restrict__ b1,
                                                      const float* __restrict__ b2,
                                                      const float* __restrict__ gw,
                                                      const float* __restrict__ gb) {
    char* xsb[2] = { sm12, sm12 + 49152 };
    char* wsb[2] = { sm12 + 32768, sm12 + 81920 };
    float* hsf = (float*)sm12;
    __shared__ float gws[DD * EE];
    __shared__ float sps[EE];

    const int t = threadIdx.x, lane = t & 31, w = t >> 5;
    const int g = lane >> 2, tg = lane & 3;
    const int row0 = (w & 3) * 32, nb = (w >> 2) * 32;
    const int tb = blockIdx.x;
    const int tok0 = tb * 128;
    const char* xtiles = g_xs + (size_t)tb * 3 * ATB;

    // prefetch chunk 0 (x tile + W1c0) as one group
    stage_xs_async(xsb[0], xtiles, t);
    stage_ws_async(wsb[0], g_wsp, t);
    CPA_COMMIT();

    gws[t] = gw[t];
    if (t < EE) sps[t] = 0.0f;

    float acc1[2][4][4];
#pragma unroll
    for (int mt = 0; mt < 2; ++mt)
#pragma unroll
        for (int j = 0; j < 4; ++j)
#pragma unroll
            for (int c = 0; c < 4; ++c) acc1[mt][j][c] = 0.0f;

    for (int it = 0; it < 3; ++it) {
        if (it) __syncthreads();      // prev gemm done with buffers
        // prefetch next group: x(it+1) (if any) + W(it+1 or W2)
        if (it < 2)
            stage_xs_async(xsb[(it + 1) & 1], xtiles + (size_t)(it + 1) * ATB, t);
        stage_ws_async(wsb[(it + 1) & 1],
                       g_wsp + (size_t)(it < 2 ? it + 1 : 3) * WTB, t);
        CPA_COMMIT();

        CPA_WAIT1();                  // group(it) landed
        __syncthreads();

        gemm_m32n32(acc1, xsb[it & 1], wsb[it & 1], row0, nb, g, tg);
    }

    // GEMM1 epilogue: h1 = gelu(acc1 + b1) -> xs1 (split, swizzled)
    // (xs1 last read at end of it=1; all warps synced since)
#pragma unroll
    for (int mt = 0; mt < 2; ++mt)
#pragma unroll
        for (int j = 0; j < 4; ++j) {
            int n0 = nb + j * 8 + 2 * tg;
            int wn = n0 >> 1;
            float bx = __ldg(&b1[n0]), by = __ldg(&b1[n0 + 1]);
            int r = row0 + mt * 16 + g;
            *(uint2*)(xsb[1] + aoff(r, wn)) =
                split_bf2(gelu_f(acc1[mt][j][0] + bx), gelu_f(acc1[mt][j][1] + by));
            *(uint2*)(xsb[1] + aoff(r + 8, wn)) =
                split_bf2(gelu_f(acc1[mt][j][2] + bx), gelu_f(acc1[mt][j][3] + by));
        }
    CPA_WAIT0();                      // W2 landed in ws1
    __syncthreads();

    float acc2[2][4][4];
#pragma unroll
    for (int mt = 0; mt < 2; ++mt)
#pragma unroll
        for (int j = 0; j < 4; ++j)
#pragma unroll
            for (int c = 0; c < 4; ++c) acc2[mt][j][c] = 0.0f;

    gemm_m32n32(acc2, xsb[1], wsb[1], row0, nb, g, tg);

    // GEMM2 epilogue: h -> g_hb (bf16 pairs) + hsf (fp32 gate scratch)
#pragma unroll
    for (int mt = 0; mt < 2; ++mt)
#pragma unroll
        for (int j = 0; j < 4; ++j) {
            int n0 = nb + j * 8 + 2 * tg;
            int wn = n0 >> 1;
            float bx = __ldg(&b2[n0]), by = __ldg(&b2[n0 + 1]);
            int r = row0 + mt * 16 + g;
            float h00 = acc2[mt][j][0] + bx, h01 = acc2[mt][j][1] + by;
            float h10 = acc2[mt][j][2] + bx, h11 = acc2[mt][j][3] + by;
            g_hb[(size_t)(tok0 + r) * 32 + wn]     = pack_bf2(h00, h01);
            g_hb[(size_t)(tok0 + r + 8) * 32 + wn] = pack_bf2(h10, h11);
            hsf[r * 65 + n0] = h00;       hsf[r * 65 + n0 + 1] = h01;
            hsf[(r + 8) * 65 + n0] = h10; hsf[(r + 8) * 65 + n0 + 1] = h11;
        }
    __syncthreads();

    if (t < 128) {
        int tok = tok0 + t;
        float lg0 = gb[0], lg1 = gb[1], lg2 = gb[2], lg3 = gb[3];
#pragma unroll 16
        for (int d = 0; d < 64; ++d) {
            float h = hsf[t * 65 + d];
            const float* g4 = &gws[d * EE];
            lg0 += h * g4[0]; lg1 += h * g4[1]; lg2 += h * g4[2]; lg3 += h * g4[3];
        }
        float m = fmaxf(fmaxf(lg0, lg1), fmaxf(lg2, lg3));
        float e0 = expf(lg0 - m), e1 = expf(lg1 - m);
        float e2 = expf(lg2 - m), e3 = expf(lg3 - m);
        float inv = 1.0f / (e0 + e1 + e2 + e3);
        float p0 = e0 * inv, p1 = e1 * inv, p2 = e2 * inv, p3 = e3 * inv;
        int am = 0; float best = lg0;
        if (lg1 > best) { best = lg1; am = 1; }
        if (lg2 > best) { best = lg2; am = 2; }
        if (lg3 > best) { best = lg3; am = 3; }
        float pe[4] = {p0, p1, p2, p3};
        g_gate[tok] = pe[am];
        int pos = atomicAdd(&g_cnt[am], 1);
        g_idx[(size_t)am * TT + pos] = tok;
        atomicAdd(&sps[0], p0); atomicAdd(&sps[1], p1);
        atomicAdd(&sps[2], p2); atomicAdd(&sps[3], p3);
    }
    __syncthreads();
    if (t < EE) atomicAdd(&g_psum[t], sps[t]);
}

// ------------------- k3: per-expert FFN (A-x1 / B-x2, ldmatrix) -------------
// dyn smem: hs @0 (16K) | hc @16384 (16K) | ws0 @32768 | ws1 @49152  (65536 B)
extern __shared__ char sm3[];
__global__ void __launch_bounds__(256, 2) k3_expert(const float* __restrict__ eb1,
                                                    const float* __restrict__ eb2) {
    const int e = blockIdx.y;
    const int base = blockIdx.x * 128;
    const int cnt = g_cnt[e];
    if (base >= cnt) return;
    const int n = min(128, cnt - base);

    char* hs  = sm3;
    char* hc  = sm3 + 16384;
    char* ws0 = sm3 + 32768;
    char* ws1 = sm3 + 49152;
    __shared__ int   stok[128];
    __shared__ float sgate[128];

    const int t = threadIdx.x, lane = t & 31, w = t >> 5;
    const int g = lane >> 2, tg = lane & 3;
    const int row0 = (w & 3) * 32, nb = (w >> 2) * 32;

    const char* W1base = g_wsp + (size_t)(4 + e * 4) * WTB;
    const char* W2base = g_wsp + (size_t)(20 + e * 4) * WTB;
    const float* b1e = eb1 + (size_t)e * HID;
    const float* b2e = eb2 + (size_t)e * DD;

    stage_ws_async(ws0, W1base, t);
    CPA_COMMIT();

    if (t < 128) {
        if (t < n) {
            int tok = g_idx[(size_t)e * TT + base + t];
            stok[t] = tok; sgate[t] = g_gate[tok];
        } else { stok[t] = -1; sgate[t] = 0.0f; }
    }
    __syncthreads();

    {   // gather bf16 h rows (128B each): 4x LDG.128 -> 4x STS.128
        int row = t >> 1, half = t & 1;
        int tok = stok[row];
        int sw = (row & 7) << 4;
        if (tok >= 0) {
            const uint4* src = (const uint4*)(g_hb + (size_t)tok * 32 + half * 16);
#pragma unroll
            for (int q = 0; q < 4; ++q) {
                uint4 v = src[q];
                *(uint4*)(hs + row * 128 + ((half * 64 + q * 16) ^ sw)) = v;
            }
        } else {
            uint4 z; z.x = z.y = z.z = z.w = 0u;
#pragma unroll
            for (int q = 0; q < 4; ++q)
                *(uint4*)(hs + row * 128 + ((half * 64 + q * 16) ^ sw)) = z;
        }
    }

    const unsigned hsA = su32(hs), hcA = su32(hc);

    float acc2[2][4][4];
#pragma unroll
    for (int mt = 0; mt < 2; ++mt)
#pragma unroll
        for (int j = 0; j < 4; ++j)
#pragma unroll
            for (int c = 0; c < 4; ++c) acc2[mt][j][c] = 0.0f;

    for (int ch = 0; ch < HID / 64; ++ch) {
        if (ch) __syncthreads();

        stage_ws_async(ws1, W2base + (size_t)ch * WTB, t);
        CPA_COMMIT();

        CPA_WAIT1();
        __syncthreads();

        float acc1[2][4][4];
#pragma unroll
        for (int mt = 0; mt < 2; ++mt)
#pragma unroll
            for (int j = 0; j < 4; ++j)
#pragma unroll
                for (int c = 0; c < 4; ++c) acc1[mt][j][c] = 0.0f;

        gemm_x1(acc1, hsA, ws0, row0, nb, lane);

        // gelu -> hc (plain bf16 pairs, swizzled 128B rows)
#pragma unroll
        for (int mt = 0; mt < 2; ++mt)
#pragma unroll
            for (int j = 0; j < 4; ++j) {
                int n0 = nb + j * 8 + 2 * tg;
                float bx = __ldg(&b1e[ch * 64 + n0]);
                float by = __ldg(&b1e[ch * 64 + n0 + 1]);
                int r = row0 + mt * 16 + g;
                unsigned p0 = pack_bf2(gelu_f(acc1[mt][j][0] + bx),
                                       gelu_f(acc1[mt][j][1] + by));
                unsigned p1 = pack_bf2(gelu_f(acc1[mt][j][2] + bx),
                                       gelu_f(acc1[mt][j][3] + by));
                *(unsigned*)(hc + r * 128 + ((n0 * 2) ^ ((r & 7) << 4)))         = p0;
                *(unsigned*)(hc + (r + 8) * 128 + ((n0 * 2) ^ (((r + 8) & 7) << 4))) = p1;
            }
        __syncthreads();

        if (ch < HID / 64 - 1) {
            stage_ws_async(ws0, W1base + (size_t)(ch + 1) * WTB, t);
            CPA_COMMIT();
            CPA_WAIT1();
        } else {
            CPA_WAIT0();
        }
        __syncthreads();

        gemm_x1(acc2, hcA, ws1, row0, nb, lane);
    }

    // scatter per-token moe output (scaled by gate) into g_h1
#pragma unroll
    for (int mt = 0; mt < 2; ++mt)
#pragma unroll
        for (int j = 0; j < 4; ++j) {
            int n0 = nb + j * 8 + 2 * tg;
            float bx = __ldg(&b2e[n0]), by = __ldg(&b2e[n0 + 1]);
            int r = row0 + mt * 16 + g;
            if (stok[r] >= 0) {
                int tok = stok[r]; float gv = sgate[r];
                float2 v;
                v.x = (acc2[mt][j][0] + bx) * gv;
                v.y = (acc2[mt][j][1] + by) * gv;
                *(float2*)&g_h1[(size_t)tok * DD + n0] = v;
            }
            if (stok[r + 8] >= 0) {
                int tok = stok[r + 8]; float gv = sgate[r + 8];
                float2 v;
                v.x = (acc2[mt][j][2] + bx) * gv;
                v.y = (acc2[mt][j][3] + by) * gv;
                *(float2*)&g_h1[(size_t)tok * DD + n0] = v;
            }
        }
}

// ------------------- k3b: deterministic mean over S ------------------------
__global__ void __launch_bounds__(256) k3b_reduce() {
    __shared__ float red[4][64];
    int b = blockIdx.x, t = threadIdx.x;
    int d = t & 63, grp = t >> 6;
    const float* src = g_h1 + (size_t)b * SS * DD;
    float s = 0.0f;
    for (int i = grp * 256; i < grp * 256 + 256; ++i)
        s += src[(size_t)i * DD + d];
    red[grp][d] = s;
    __syncthreads();
    if (t < 64)
        g_z[b * DD + t] = (red[0][t] + red[1][t] + red[2][t] + red[3][t]) * (1.0f / (float)SS);
}

// ------------------- k4: LayerNorm + classifier + aux loss -----------------
__global__ void k4_cls(const float* __restrict__ lng, const float* __restrict__ lnb,
                       const float* __restrict__ w1,  const float* __restrict__ b1,
                       const float* __restrict__ w2,  const float* __restrict__ b2,
                       float* __restrict__ out, int out_size) {
    int b = threadIdx.x;
    float zr[DD];
    float s = 0.0f;
#pragma unroll
    for (int d = 0; d < DD; ++d) { float v = g_z[b * DD + d]; zr[d] = v; s += v; }
    float mu = s * (1.0f / DD);
    float ss2 = 0.0f;
#pragma unroll
    for (int d = 0; d < DD; ++d) { float c = zr[d] - mu; ss2 += c * c; }
    float inv = rsqrtf(ss2 * (1.0f / DD) + 1e-5f);
#pragma unroll
    for (int d = 0; d < DD; ++d)
        zr[d] = (zr[d] - mu) * inv * lng[d] + lnb[d];

    float h[DD];
#pragma unroll
    for (int o = 0; o < DD; ++o) h[o] = b1[o];
    for (int d = 0; d < DD; ++d) {
        float zd = zr[d];
#pragma unroll
        for (int o = 0; o < DD; ++o) h[o] += zd * w1[d * DD + o];
    }
#pragma unroll
    for (int o = 0; o < DD; ++o) h[o] = gelu_f(h[o]);

    float y[NCLS];
#pragma unroll
    for (int c = 0; c < NCLS; ++c) y[c] = b2[c];
    for (int o = 0; o < DD; ++o) {
        float ho = h[o];
#pragma unroll
        for (int c = 0; c < NCLS; ++c) y[c] += ho * w2[o * NCLS + c];
    }
#pragma unroll
    for (int c = 0; c < NCLS; ++c) out[b * NCLS + c] = y[c];

    if (b == 0) {
        float aux = 0.0f;
        for (int e = 0; e < EE; ++e) {
            float f = (float)g_cnt[e] / (float)TT;
            float p = g_psum[e] / (float)TT;
            aux += f * p;
        }
        out[out_size - 1] = (float)EE * aux;
    }
}

// ----------------------------- launch ---------------------------------------
extern "C" void kernel_launch(void* const* d_in, const int* in_sizes, int n_in,
                              void* d_out, int out_size) {
    const float* x      = (const float*)d_in[0];
    const float* pe_w1  = (const float*)d_in[1];
    const float* pe_b1  = (const float*)d_in[2];
    const float* pe_w2  = (const float*)d_in[3];
    const float* pe_b2  = (const float*)d_in[4];
    const float* gate_w = (const float*)d_in[5];
    const float* gate_b = (const float*)d_in[6];
    const float* ew1    = (const float*)d_in[7];
    const float* eb1    = (const float*)d_in[8];
    const float* ew2    = (const float*)d_in[9];
    const float* eb2    = (const float*)d_in[10];
    const float* ln_g   = (const float*)d_in[11];
    const float* ln_b   = (const float*)d_in[12];
    const float* cl_w1  = (const float*)d_in[13];
    const float* cl_b1  = (const float*)d_in[14];
    const float* cl_w2  = (const float*)d_in[15];
    const float* cl_b2  = (const float*)d_in[16];

    const int smem12 = 98304;
    const int smem3  = 65536;
    cudaFuncSetAttribute(k12_pe_gate, cudaFuncAttributeMaxDynamicSharedMemorySize, smem12);
    cudaFuncSetAttribute(k3_expert,   cudaFuncAttributeMaxDynamicSharedMemorySize, smem3);

    k_pre<<<36, 256>>>(pe_w1, pe_w2, ew1, ew2);
    k_xsplit<<<dim3(TT / 128, 3), 256>>>(x);
    k0_zero<<<1, 32>>>();
    k12_pe_gate<<<TT / 128, 256, smem12>>>(pe_b1, pe_b2, gate_w, gate_b);
    k3_expert<<<dim3(TT / 128, EE), 256, smem3>>>(eb1, eb2);
    k3b_reduce<<<BB, 256>>>();
    k4_cls<<<1, 128>>>(ln_g, ln_b, cl_w1, cl_b1, cl_w2, cl_b2,
                       (float*)d_out, out_size);
}

// round 14
// speedup vs baseline: 1.0822x; 1.0822x over previous
#include <cuda_runtime.h>
#include <cuda_bf16.h>
#include <math.h>

#define BB   128
#define SS   1024
#define TT   (BB*SS)          // 131072 tokens
#define IND  192
#define DD   64
#define EE   4
#define HID  256
#define NCLS 10

#define ATB 32768             // split activation tile: 128 rows x 256B
#define WTB 16384             // weight chunk: 64 rows x 256B (hi/lo pairs)

// ------------------------- scratch (device globals) ------------------------
__device__ float g_h1[(size_t)TT * DD];                // moe output buffer
__device__ __align__(16) unsigned g_hb[(size_t)TT * 32]; // h as bf16 pairs
__device__ float g_gate[TT];
__device__ int   g_idx[(size_t)EE * TT];
__device__ int   g_cnt[EE];
__device__ float g_psum[EE];
__device__ float g_z[BB * DD];
// pre-split bf16 weights, 36 chunks, swizzled smem image [n][kw] uint2{hi,lo}
__device__ __align__(16) char g_wsp[(size_t)36 * WTB];
// pre-split x: 1024 token-tiles x 3 K-chunks, exact swizzled smem images
__device__ __align__(16) char g_xs[(size_t)3072 * ATB];

__device__ __forceinline__ float gelu_f(float v) {
    return 0.5f * v * (1.0f + erff(v * 0.70710678118654752440f));
}
__device__ __forceinline__ uint2 split_bf2(float x0, float x1) {
    __nv_bfloat16 h0 = __float2bfloat16_rn(x0), h1 = __float2bfloat16_rn(x1);
    float f0 = __bfloat162float(h0), f1 = __bfloat162float(h1);
    __nv_bfloat16 l0 = __float2bfloat16_rn(x0 - f0), l1 = __float2bfloat16_rn(x1 - f1);
    uint2 r;
    r.x = ((unsigned)__bfloat16_as_ushort(h1) << 16) | __bfloat16_as_ushort(h0);
    r.y = ((unsigned)__bfloat16_as_ushort(l1) << 16) | __bfloat16_as_ushort(l0);
    return r;
}
__device__ __forceinline__ unsigned pack_bf2(float x0, float x1) {
    __nv_bfloat162 p = __floats2bfloat162_rn(x0, x1);
    return *(unsigned*)&p;
}
// split-tile addressing (256B rows): word w (0..31 = k-pair), pairs (w,w+4)
__device__ __forceinline__ int aphys(int w) {
    int u = w & 7;
    return ((w >> 3) << 6) + (((((u & 3) << 1) | (u >> 2))) << 3);
}
__device__ __forceinline__ int aoff(int row, int w) {
    return row * 256 + (aphys(w) ^ ((row & 1) << 6));
}
__device__ __forceinline__ unsigned su32(const void* p) {
    return (unsigned)__cvta_generic_to_shared(p);
}
__device__ __forceinline__ void cpa16(unsigned dst, const void* src) {
    asm volatile("cp.async.cg.shared.global [%0], [%1], 16;" :: "r"(dst), "l"(src));
}
#define CPA_COMMIT() asm volatile("cp.async.commit_group;" ::: "memory")
#define CPA_WAIT0()  asm volatile("cp.async.wait_group 0;" ::: "memory")
#define CPA_WAIT1()  asm volatile("cp.async.wait_group 1;" ::: "memory")

__device__ __forceinline__ void stage_ws_async(char* dst, const char* src, int t) {
    unsigned d = su32(dst);
    for (int i = t; i < WTB / 16; i += 256)
        cpa16(d + i * 16, src + i * 16);
}
__device__ __forceinline__ void stage_xs_async(char* dst, const char* src, int t) {
    unsigned d = su32(dst);
    for (int i = t; i < ATB / 16; i += 256)
        cpa16(d + i * 16, src + i * 16);
}

__device__ __forceinline__ void mmabf(float* c, const unsigned* a, unsigned b0, unsigned b1) {
    asm volatile(
        "mma.sync.aligned.m16n8k16.row.col.f32.bf16.bf16.f32 "
        "{%0,%1,%2,%3},{%4,%5,%6,%7},{%8,%9},{%0,%1,%2,%3};"
        : "+f"(c[0]), "+f"(c[1]), "+f"(c[2]), "+f"(c[3])
        : "r"(a[0]), "r"(a[1]), "r"(a[2]), "r"(a[3]), "r"(b0), "r"(b1));
}
__device__ __forceinline__ void mma3bf(float* c, const unsigned* aH, const unsigned* aL,
                                       unsigned bH0, unsigned bH1,
                                       unsigned bL0, unsigned bL1) {
    mmabf(c, aL, bH0, bH1);
    mmabf(c, aH, bL0, bL1);
    mmabf(c, aH, bH0, bH1);
}
__device__ __forceinline__ void ldm4(unsigned* a, unsigned addr) {
    asm volatile("ldmatrix.sync.aligned.m8n8.x4.shared.b16 {%0,%1,%2,%3}, [%4];"
        : "=r"(a[0]), "=r"(a[1]), "=r"(a[2]), "=r"(a[3]) : "r"(addr));
}

// ---- k12 GEMM: x3 over split tiles ----------------------------------------
__device__ __forceinline__ void gemm_m32n32(float acc[2][4][4],
                                            const char* A, const char* W,
                                            int row0, int nb, int g, int tg) {
    const int pg = (g & 1) << 6;
    const char* a0p = A + (row0 + g) * 256;
    const char* a1p = A + (row0 + 8 + g) * 256;
    const char* a2p = A + (row0 + 16 + g) * 256;
    const char* a3p = A + (row0 + 24 + g) * 256;
    const char* bp  = W + (nb + g) * 256;
#pragma unroll
    for (int kg = 0; kg < 4; ++kg) {
        int C = ((kg << 6) ^ pg) + (tg << 4);
        uint4 A0 = *(const uint4*)(a0p + C);
        uint4 A1 = *(const uint4*)(a1p + C);
        uint4 A2 = *(const uint4*)(a2p + C);
        uint4 A3 = *(const uint4*)(a3p + C);
        unsigned aH0[4] = {A0.x, A1.x, A0.z, A1.z};
        unsigned aL0[4] = {A0.y, A1.y, A0.w, A1.w};
        unsigned aH1[4] = {A2.x, A3.x, A2.z, A3.z};
        unsigned aL1[4] = {A2.y, A3.y, A2.w, A3.w};
#pragma unroll
        for (int j = 0; j < 4; ++j) {
            uint4 B = *(const uint4*)(bp + j * 2048 + C);
            mma3bf(acc[0][j], aH0, aL0, B.x, B.z, B.y, B.w);
            mma3bf(acc[1][j], aH1, aL1, B.x, B.z, B.y, B.w);
        }
    }
}

// ---- k3 GEMM: A plain bf16 (ldmatrix, 128B rows), B x2 hi/lo ---------------
__device__ __forceinline__ void gemm_x1(float acc[2][4][4],
                                        unsigned Abase, const char* W,
                                        int row0, int nb, int lane) {
    const int g = lane >> 2, tg = lane & 3;
    const int li = lane & 7, grp = lane >> 3;
    const int rsub = ((grp & 1) << 3) + li;
    const int khalf = (grp >> 1) << 4;
    const int r0a = row0 + rsub, r1a = row0 + 16 + rsub;
    const unsigned a0base = Abase + r0a * 128;
    const unsigned a1base = Abase + r1a * 128;
    const int sw0 = (r0a & 7) << 4, sw1 = (r1a & 7) << 4;
    const char* bp = W + (nb + g) * 256;
    const int pg = (g & 1) << 6;
#pragma unroll
    for (int kg = 0; kg < 4; ++kg) {
        int kb = kg * 32 + khalf;
        unsigned A0[4], A1[4];
        ldm4(A0, a0base + (unsigned)(kb ^ sw0));
        ldm4(A1, a1base + (unsigned)(kb ^ sw1));
        int C = ((kg << 6) ^ pg) + (tg << 4);
#pragma unroll
        for (int j = 0; j < 4; ++j) {
            uint4 B = *(const uint4*)(bp + j * 2048 + C);
            mmabf(acc[0][j], A0, B.x, B.z);
            mmabf(acc[0][j], A0, B.y, B.w);
            mmabf(acc[1][j], A1, B.x, B.z);
            mmabf(acc[1][j], A1, B.y, B.w);
        }
    }
}

// ------------------------- k_pre: split+layout all weights ------------------
__global__ void __launch_bounds__(256) k_pre(const float* __restrict__ pw1,
                                             const float* __restrict__ pw2,
                                             const float* __restrict__ ew1,
                                             const float* __restrict__ ew2) {
    const int cid = blockIdx.x, t = threadIdx.x;
    char* dst = g_wsp + (size_t)cid * WTB;
#pragma unroll
    for (int p = 0; p < 8; ++p) {
        int idx = p * 256 + t;
        int kw = idx >> 6, n = idx & 63;
        int k0 = 2 * kw, k1 = 2 * kw + 1;
        float v0, v1;
        if (cid < 3) {
            v0 = pw1[(size_t)(cid * 64 + k0) * DD + n];
            v1 = pw1[(size_t)(cid * 64 + k1) * DD + n];
        } else if (cid == 3) {
            v0 = pw2[(size_t)k0 * DD + n];
            v1 = pw2[(size_t)k1 * DD + n];
        } else if (cid < 20) {
            int e = (cid - 4) >> 2, ch = (cid - 4) & 3;
            const float* w = ew1 + (size_t)e * DD * HID + ch * 64 + n;
            v0 = w[(size_t)k0 * HID];
            v1 = w[(size_t)k1 * HID];
        } else {
            int e = (cid - 20) >> 2, ch = (cid - 20) & 3;
            const float* w = ew2 + (size_t)e * HID * DD + (size_t)ch * 64 * DD + n;
            v0 = w[(size_t)k0 * DD];
            v1 = w[(size_t)k1 * DD];
        }
        *(uint2*)(dst + aoff(n, kw)) = split_bf2(v0, v1);
    }
}

// ------------------- k_xsplit: x -> swizzled split tiles (dense stores) -----
// Inverse-permutation mapping: lane owns physical 16B slot s of row; derives
// which k-pairs live there: bb = s ^ ((row&1)<<2), wlo = (bb>>2)*8 + (bb&3),
// beat = {split(x[2wlo],x[2wlo+1]), split(x[2wlo+8],x[2wlo+9])}.
// Warp stores 512B dense; warp loads cover whole 32B sectors.
__global__ void __launch_bounds__(256) k_xsplit(const float* __restrict__ x) {
    const int tb = blockIdx.x, it = blockIdx.y;
    const int t = threadIdx.x, lane = t & 31, w = t >> 5;
    char* dst = g_xs + ((size_t)tb * 3 + it) * ATB;
    const int rl = lane >> 4;          // row parity within pair
    const int s  = lane & 15;          // 16B slot within 256B row
    const int bb = s ^ (rl << 2);
    const int wlo = (bb >> 2) * 8 + (bb & 3);
#pragma unroll
    for (int i = 0; i < 8; ++i) {
        int row = (w * 8 + i) * 2 + rl;
        const float* xr = x + (size_t)(tb * 128 + row) * IND + it * 64;
        float2 p0 = *(const float2*)(xr + 2 * wlo);
        float2 p1 = *(const float2*)(xr + 2 * wlo + 8);
        uint2 a = split_bf2(p0.x, p0.y);
        uint2 b = split_bf2(p1.x, p1.y);
        uint4 beat; beat.x = a.x; beat.y = a.y; beat.z = b.x; beat.w = b.y;
        *(uint4*)(dst + row * 256 + s * 16) = beat;
    }
}

// ------------------------- k0: zero counters -------------------------------
__global__ void k0_zero() {
    int t = threadIdx.x;
    if (t < EE) { g_cnt[t] = 0; g_psum[t] = 0.0f; }
}

// ------------- k12: fused patch-encoder (both layers) + gate ---------------
// dyn smem: xs0 @0 | ws0 @32768 | xs1 @49152 | ws1 @81920  (98304 B)
// gate scratch hsf (128x65 fp32) overlays xs0+ws0 (dead at gate time)
extern __shared__ char sm12[];
__global__ void __launch_bounds__(256, 2) k12_pe_gate(const float* __restrict__ b1,
                                                      const float* __restrict__ b2,
                                                      const float* __restrict__ gw,
                                                      const float* __restrict__ gb) {
    char* xsb[2] = { sm12, sm12 + 49152 };
    char* wsb[2] = { sm12 + 32768, sm12 + 81920 };
    float* hsf = (float*)sm12;
    __shared__ float gws[DD * EE];
    __shared__ float sps[EE];

    const int t = threadIdx.x, lane = t & 31, w = t >> 5;
    const int g = lane >> 2, tg = lane & 3;
    const int row0 = (w & 3) * 32, nb = (w >> 2) * 32;
    const int tb = blockIdx.x;
    const int tok0 = tb * 128;
    const char* xtiles = g_xs + (size_t)tb * 3 * ATB;

    // prefetch chunk 0 (x tile + W1c0) as one group
    stage_xs_async(xsb[0], xtiles, t);
    stage_ws_async(wsb[0], g_wsp, t);
    CPA_COMMIT();

    gws[t] = gw[t];
    if (t < EE) sps[t] = 0.0f;

    float acc1[2][4][4];
#pragma unroll
    for (int mt = 0; mt < 2; ++mt)
#pragma unroll
        for (int j = 0; j < 4; ++j)
#pragma unroll
            for (int c = 0; c < 4; ++c) acc1[mt][j][c] = 0.0f;

    for (int it = 0; it < 3; ++it) {
        if (it) __syncthreads();      // prev gemm done with buffers
        if (it < 2)
            stage_xs_async(xsb[(it + 1) & 1], xtiles + (size_t)(it + 1) * ATB, t);
        stage_ws_async(wsb[(it + 1) & 1],
                       g_wsp + (size_t)(it < 2 ? it + 1 : 3) * WTB, t);
        CPA_COMMIT();

        CPA_WAIT1();                  // group(it) landed
        __syncthreads();

        gemm_m32n32(acc1, xsb[it & 1], wsb[it & 1], row0, nb, g, tg);
    }

    // GEMM1 epilogue: h1 = gelu(acc1 + b1) -> xs1 (split, swizzled)
#pragma unroll
    for (int mt = 0; mt < 2; ++mt)
#pragma unroll
        for (int j = 0; j < 4; ++j) {
            int n0 = nb + j * 8 + 2 * tg;
            int wn = n0 >> 1;
            float bx = __ldg(&b1[n0]), by = __ldg(&b1[n0 + 1]);
            int r = row0 + mt * 16 + g;
            *(uint2*)(xsb[1] + aoff(r, wn)) =
                split_bf2(gelu_f(acc1[mt][j][0] + bx), gelu_f(acc1[mt][j][1] + by));
            *(uint2*)(xsb[1] + aoff(r + 8, wn)) =
                split_bf2(gelu_f(acc1[mt][j][2] + bx), gelu_f(acc1[mt][j][3] + by));
        }
    CPA_WAIT0();                      // W2 landed in ws1
    __syncthreads();

    float acc2[2][4][4];
#pragma unroll
    for (int mt = 0; mt < 2; ++mt)
#pragma unroll
        for (int j = 0; j < 4; ++j)
#pragma unroll
            for (int c = 0; c < 4; ++c) acc2[mt][j][c] = 0.0f;

    gemm_m32n32(acc2, xsb[1], wsb[1], row0, nb, g, tg);

    // GEMM2 epilogue: h -> g_hb (bf16 pairs) + hsf (fp32 gate scratch)
#pragma unroll
    for (int mt = 0; mt < 2; ++mt)
#pragma unroll
        for (int j = 0; j < 4; ++j) {
            int n0 = nb + j * 8 + 2 * tg;
            int wn = n0 >> 1;
            float bx = __ldg(&b2[n0]), by = __ldg(&b2[n0 + 1]);
            int r = row0 + mt * 16 + g;
            float h00 = acc2[mt][j][0] + bx, h01 = acc2[mt][j][1] + by;
            float h10 = acc2[mt][j][2] + bx, h11 = acc2[mt][j][3] + by;
            g_hb[(size_t)(tok0 + r) * 32 + wn]     = pack_bf2(h00, h01);
            g_hb[(size_t)(tok0 + r + 8) * 32 + wn] = pack_bf2(h10, h11);
            hsf[r * 65 + n0] = h00;       hsf[r * 65 + n0 + 1] = h01;
            hsf[(r + 8) * 65 + n0] = h10; hsf[(r + 8) * 65 + n0 + 1] = h11;
        }
    __syncthreads();

    if (t < 128) {
        int tok = tok0 + t;
        float lg0 = gb[0], lg1 = gb[1], lg2 = gb[2], lg3 = gb[3];
#pragma unroll 16
        for (int d = 0; d < 64; ++d) {
            float h = hsf[t * 65 + d];
            const float* g4 = &gws[d * EE];
            lg0 += h * g4[0]; lg1 += h * g4[1]; lg2 += h * g4[2]; lg3 += h * g4[3];
        }
        float m = fmaxf(fmaxf(lg0, lg1), fmaxf(lg2, lg3));
        float e0 = expf(lg0 - m), e1 = expf(lg1 - m);
        float e2 = expf(lg2 - m), e3 = expf(lg3 - m);
        float inv = 1.0f / (e0 + e1 + e2 + e3);
        float p0 = e0 * inv, p1 = e1 * inv, p2 = e2 * inv, p3 = e3 * inv;
        int am = 0; float best = lg0;
        if (lg1 > best) { best = lg1; am = 1; }
        if (lg2 > best) { best = lg2; am = 2; }
        if (lg3 > best) { best = lg3; am = 3; }
        float pe[4] = {p0, p1, p2, p3};
        g_gate[tok] = pe[am];
        int pos = atomicAdd(&g_cnt[am], 1);
        g_idx[(size_t)am * TT + pos] = tok;
        atomicAdd(&sps[0], p0); atomicAdd(&sps[1], p1);
        atomicAdd(&sps[2], p2); atomicAdd(&sps[3], p3);
    }
    __syncthreads();
    if (t < EE) atomicAdd(&g_psum[t], sps[t]);
}

// ------------------- k3: per-expert FFN (A-x1 / B-x2, ldmatrix) -------------
// dyn smem: hs @0 (16K) | hc @16384 (16K) | ws0 @32768 | ws1 @49152  (65536 B)
extern __shared__ char sm3[];
__global__ void __launch_bounds__(256, 2) k3_expert(const float* __restrict__ eb1,
                                                    const float* __restrict__ eb2) {
    const int e = blockIdx.y;
    const int base = blockIdx.x * 128;
    const int cnt = g_cnt[e];
    if (base >= cnt) return;
    const int n = min(128, cnt - base);

    char* hs  = sm3;
    char* hc  = sm3 + 16384;
    char* ws0 = sm3 + 32768;
    char* ws1 = sm3 + 49152;
    __shared__ int   stok[128];
    __shared__ float sgate[128];

    const int t = threadIdx.x, lane = t & 31, w = t >> 5;
    const int g = lane >> 2, tg = lane & 3;
    const int row0 = (w & 3) * 32, nb = (w >> 2) * 32;

    const char* W1base = g_wsp + (size_t)(4 + e * 4) * WTB;
    const char* W2base = g_wsp + (size_t)(20 + e * 4) * WTB;
    const float* b1e = eb1 + (size_t)e * HID;
    const float* b2e = eb2 + (size_t)e * DD;

    stage_ws_async(ws0, W1base, t);
    CPA_COMMIT();

    if (t < 128) {
        if (t < n) {
            int tok = g_idx[(size_t)e * TT + base + t];
            stok[t] = tok; sgate[t] = g_gate[tok];
        } else { stok[t] = -1; sgate[t] = 0.0f; }
    }
    __syncthreads();

    {   // gather bf16 h rows (128B each): 4x LDG.128 -> 4x STS.128
        int row = t >> 1, half = t & 1;
        int tok = stok[row];
        int sw = (row & 7) << 4;
        if (tok >= 0) {
            const uint4* src = (const uint4*)(g_hb + (size_t)tok * 32 + half * 16);
#pragma unroll
            for (int q = 0; q < 4; ++q) {
                uint4 v = src[q];
                *(uint4*)(hs + row * 128 + ((half * 64 + q * 16) ^ sw)) = v;
            }
        } else {
            uint4 z; z.x = z.y = z.z = z.w = 0u;
#pragma unroll
            for (int q = 0; q < 4; ++q)
                *(uint4*)(hs + row * 128 + ((half * 64 + q * 16) ^ sw)) = z;
        }
    }

    const unsigned hsA = su32(hs), hcA = su32(hc);

    float acc2[2][4][4];
#pragma unroll
    for (int mt = 0; mt < 2; ++mt)
#pragma unroll
        for (int j = 0; j < 4; ++j)
#pragma unroll
            for (int c = 0; c < 4; ++c) acc2[mt][j][c] = 0.0f;

    for (int ch = 0; ch < HID / 64; ++ch) {
        if (ch) __syncthreads();

        stage_ws_async(ws1, W2base + (size_t)ch * WTB, t);
        CPA_COMMIT();

        CPA_WAIT1();
        __syncthreads();

        float acc1[2][4][4];
#pragma unroll
        for (int mt = 0; mt < 2; ++mt)
#pragma unroll
            for (int j = 0; j < 4; ++j)
#pragma unroll
                for (int c = 0; c < 4; ++c) acc1[mt][j][c] = 0.0f;

        gemm_x1(acc1, hsA, ws0, row0, nb, lane);

        // gelu -> hc (plain bf16 pairs, swizzled 128B rows)
#pragma unroll
        for (int mt = 0; mt < 2; ++mt)
#pragma unroll
            for (int j = 0; j < 4; ++j) {
                int n0 = nb + j * 8 + 2 * tg;
                float bx = __ldg(&b1e[ch * 64 + n0]);
                float by = __ldg(&b1e[ch * 64 + n0 + 1]);
                int r = row0 + mt * 16 + g;
                unsigned p0 = pack_bf2(gelu_f(acc1[mt][j][0] + bx),
                                       gelu_f(acc1[mt][j][1] + by));
                unsigned p1 = pack_bf2(gelu_f(acc1[mt][j][2] + bx),
                                       gelu_f(acc1[mt][j][3] + by));
                *(unsigned*)(hc + r * 128 + ((n0 * 2) ^ ((r & 7) << 4)))         = p0;
                *(unsigned*)(hc + (r + 8) * 128 + ((n0 * 2) ^ (((r + 8) & 7) << 4))) = p1;
            }
        __syncthreads();

        if (ch < HID / 64 - 1) {
            stage_ws_async(ws0, W1base + (size_t)(ch + 1) * WTB, t);
            CPA_COMMIT();
            CPA_WAIT1();
        } else {
            CPA_WAIT0();
        }
        __syncthreads();

        gemm_x1(acc2, hcA, ws1, row0, nb, lane);
    }

    // scatter per-token moe output (scaled by gate) into g_h1
#pragma unroll
    for (int mt = 0; mt < 2; ++mt)
#pragma unroll
        for (int j = 0; j < 4; ++j) {
            int n0 = nb + j * 8 + 2 * tg;
            float bx = __ldg(&b2e[n0]), by = __ldg(&b2e[n0 + 1]);
            int r = row0 + mt * 16 + g;
            if (stok[r] >= 0) {
                int tok = stok[r]; float gv = sgate[r];
                float2 v;
                v.x = (acc2[mt][j][0] + bx) * gv;
                v.y = (acc2[mt][j][1] + by) * gv;
                *(float2*)&g_h1[(size_t)tok * DD + n0] = v;
            }
            if (stok[r + 8] >= 0) {
                int tok = stok[r + 8]; float gv = sgate[r + 8];
                float2 v;
                v.x = (acc2[mt][j][2] + bx) * gv;
                v.y = (acc2[mt][j][3] + by) * gv;
                *(float2*)&g_h1[(size_t)tok * DD + n0] = v;
            }
        }
}

// ------------------- k3b: deterministic mean over S ------------------------
__global__ void __launch_bounds__(256) k3b_reduce() {
    __shared__ float red[4][64];
    int b = blockIdx.x, t = threadIdx.x;
    int d = t & 63, grp = t >> 6;
    const float* src = g_h1 + (size_t)b * SS * DD;
    float s = 0.0f;
    for (int i = grp * 256; i < grp * 256 + 256; ++i)
        s += src[(size_t)i * DD + d];
    red[grp][d] = s;
    __syncthreads();
    if (t < 64)
        g_z[b * DD + t] = (red[0][t] + red[1][t] + red[2][t] + red[3][t]) * (1.0f / (float)SS);
}

// ------------------- k4: LayerNorm + classifier + aux loss -----------------
__global__ void k4_cls(const float* __restrict__ lng, const float* __restrict__ lnb,
                       const float* __restrict__ w1,  const float* __restrict__ b1,
                       const float* __restrict__ w2,  const float* __restrict__ b2,
                       float* __restrict__ out, int out_size) {
    int b = threadIdx.x;
    float zr[DD];
    float s = 0.0f;
#pragma unroll
    for (int d = 0; d < DD; ++d) { float v = g_z[b * DD + d]; zr[d] = v; s += v; }
    float mu = s * (1.0f / DD);
    float ss2 = 0.0f;
#pragma unroll
    for (int d = 0; d < DD; ++d) { float c = zr[d] - mu; ss2 += c * c; }
    float inv = rsqrtf(ss2 * (1.0f / DD) + 1e-5f);
#pragma unroll
    for (int d = 0; d < DD; ++d)
        zr[d] = (zr[d] - mu) * inv * lng[d] + lnb[d];

    float h[DD];
#pragma unroll
    for (int o = 0; o < DD; ++o) h[o] = b1[o];
    for (int d = 0; d < DD; ++d) {
        float zd = zr[d];
#pragma unroll
        for (int o = 0; o < DD; ++o) h[o] += zd * w1[d * DD + o];
    }
#pragma unroll
    for (int o = 0; o < DD; ++o) h[o] = gelu_f(h[o]);

    float y[NCLS];
#pragma unroll
    for (int c = 0; c < NCLS; ++c) y[c] = b2[c];
    for (int o = 0; o < DD; ++o) {
        float ho = h[o];
#pragma unroll
        for (int c = 0; c < NCLS; ++c) y[c] += ho * w2[o * NCLS + c];
    }
#pragma unroll
    for (int c = 0; c < NCLS; ++c) out[b * NCLS + c] = y[c];

    if (b == 0) {
        float aux = 0.0f;
        for (int e = 0; e < EE; ++e) {
            float f = (float)g_cnt[e] / (float)TT;
            float p = g_psum[e] / (float)TT;
            aux += f * p;
        }
        out[out_size - 1] = (float)EE * aux;
    }
}

// ----------------------------- launch ---------------------------------------
extern "C" void kernel_launch(void* const* d_in, const int* in_sizes, int n_in,
                              void* d_out, int out_size) {
    const float* x      = (const float*)d_in[0];
    const float* pe_w1  = (const float*)d_in[1];
    const float* pe_b1  = (const float*)d_in[2];
    const float* pe_w2  = (const float*)d_in[3];
    const float* pe_b2  = (const float*)d_in[4];
    const float* gate_w = (const float*)d_in[5];
    const float* gate_b = (const float*)d_in[6];
    const float* ew1    = (const float*)d_in[7];
    const float* eb1    = (const float*)d_in[8];
    const float* ew2    = (const float*)d_in[9];
    const float* eb2    = (const float*)d_in[10];
    const float* ln_g   = (const float*)d_in[11];
    const float* ln_b   = (const float*)d_in[12];
    const float* cl_w1  = (const float*)d_in[13];
    const float* cl_b1  = (const float*)d_in[14];
    const float* cl_w2  = (const float*)d_in[15];
    const float* cl_b2  = (const float*)d_in[16];

    const int smem12 = 98304;
    const int smem3  = 65536;
    cudaFuncSetAttribute(k12_pe_gate, cudaFuncAttributeMaxDynamicSharedMemorySize, smem12);
    cudaFuncSetAttribute(k3_expert,   cudaFuncAttributeMaxDynamicSharedMemorySize, smem3);

    k_pre<<<36, 256>>>(pe_w1, pe_w2, ew1, ew2);
    k_xsplit<<<dim3(TT / 128, 3), 256>>>(x);
    k0_zero<<<1, 32>>>();
    k12_pe_gate<<<TT / 128, 256, smem12>>>(pe_b1, pe_b2, gate_w, gate_b);
    k3_expert<<<dim3(TT / 128, EE), 256, smem3>>>(eb1, eb2);
    k3b_reduce<<<BB, 256>>>();
    k4_cls<<<1, 128>>>(ln_g, ln_b, cl_w1, cl_b1, cl_w2, cl_b2,
                       (float*)d_out, out_size);
}